// round 2
// baseline (speedup 1.0000x reference)
#include <cuda_runtime.h>
#include <math.h>

#define H 1024
#define V 50257
#define L 512

// ---------------- scratch (no allocations allowed) ----------------
__device__ float g_scores[L];        // attn scores, then reused as weights
__device__ float g_ctx[H];           // attn_applied
__device__ float g_x[H];             // GRU input
__device__ float g_hnew[H];          // new hidden
__device__ float g_logits[V];
__device__ float g_red[2];           // max, log(sumexp)

__device__ __forceinline__ float warp_sum(float v) {
    #pragma unroll
    for (int o = 16; o > 0; o >>= 1) v += __shfl_down_sync(0xffffffffu, v, o);
    return v;
}

__device__ __forceinline__ float dot4(float4 a, float4 b) {
    return a.x*b.x + a.y*b.y + a.z*b.z + a.w*b.w;
}

// ---- k1: attn scores: s[l] = attn_W[l,:] . cat(embedded, h) + attn_b[l] ----
__global__ void k_scores(const int* __restrict__ idx,
                         const float* __restrict__ emb,
                         const float* __restrict__ h,
                         const float* __restrict__ attn_W,
                         const float* __restrict__ attn_b) {
    int l = blockIdx.x;                 // 0..511
    int t = threadIdx.x;                // 256 threads
    const float4* w4 = (const float4*)(attn_W + (size_t)l * (2*H));
    const float4* e4 = (const float4*)(emb + (size_t)idx[0] * H);
    const float4* h4 = (const float4*)h;
    float acc = dot4(w4[t], e4[t]) + dot4(w4[t + 256], h4[t]);
    acc = warp_sum(acc);
    __shared__ float sm[8];
    if ((t & 31) == 0) sm[t >> 5] = acc;
    __syncthreads();
    if (t < 8) {
        float v = sm[t];
        #pragma unroll
        for (int o = 4; o > 0; o >>= 1) v += __shfl_down_sync(0xffu, v, o);
        if (t == 0) g_scores[l] = v + attn_b[l];
    }
}

// ---- k2: softmax over L=512, write attn_weights to d_out and to g_scores ----
__global__ void k_softmax(float* __restrict__ d_out) {
    int t = threadIdx.x;                 // 512 threads
    __shared__ float sm[512];
    float s = g_scores[t];
    sm[t] = s; __syncthreads();
    #pragma unroll
    for (int o = 256; o > 0; o >>= 1) {
        if (t < o) sm[t] = fmaxf(sm[t], sm[t + o]);
        __syncthreads();
    }
    float m = sm[0];
    __syncthreads();
    float e = expf(s - m);
    sm[t] = e; __syncthreads();
    #pragma unroll
    for (int o = 256; o > 0; o >>= 1) {
        if (t < o) sm[t] += sm[t + o];
        __syncthreads();
    }
    float w = e / sm[0];
    g_scores[t] = w;
    d_out[V + H + t] = w;
}

// ---- k3: ctx[col] = sum_l w[l] * enc[l, col] ---- grid 4 x 256 threads
__global__ void k_ctx(const float* __restrict__ enc) {
    __shared__ float wsh[L];
    int t = threadIdx.x;
    wsh[t] = g_scores[t];
    wsh[t + 256] = g_scores[t + 256];
    __syncthreads();
    int col = blockIdx.x * 256 + t;
    float acc = 0.f;
    #pragma unroll 8
    for (int l = 0; l < L; ++l)
        acc += wsh[l] * enc[(size_t)l * H + col];
    g_ctx[col] = acc;
}

// ---- k4: x[i] = relu(comb_W[i,:] . cat(embedded, ctx) + comb_b[i]) ----
__global__ void k_combine(const int* __restrict__ idx,
                          const float* __restrict__ emb,
                          const float* __restrict__ comb_W,
                          const float* __restrict__ comb_b) {
    int i = blockIdx.x;                 // 0..1023
    int t = threadIdx.x;                // 256 threads
    const float4* w4 = (const float4*)(comb_W + (size_t)i * (2*H));
    const float4* e4 = (const float4*)(emb + (size_t)idx[0] * H);
    const float4* c4 = (const float4*)g_ctx;
    float acc = dot4(w4[t], e4[t]) + dot4(w4[t + 256], c4[t]);
    acc = warp_sum(acc);
    __shared__ float sm[8];
    if ((t & 31) == 0) sm[t >> 5] = acc;
    __syncthreads();
    if (t < 8) {
        float v = sm[t];
        #pragma unroll
        for (int o = 4; o > 0; o >>= 1) v += __shfl_down_sync(0xffu, v, o);
        if (t == 0) g_x[i] = fmaxf(v + comb_b[i], 0.f);
    }
}

// ---- k5: GRU step, one block per output element i ----
__global__ void k_gru(const float* __restrict__ h,
                      const float* __restrict__ W_ih,
                      const float* __restrict__ W_hh,
                      const float* __restrict__ b_ih,
                      const float* __restrict__ b_hh,
                      float* __restrict__ d_out) {
    int i = blockIdx.x;                 // 0..1023
    int t = threadIdx.x;                // 256 threads, 1 float4 each
    const float4* x4 = (const float4*)g_x;
    const float4* h4 = (const float4*)h;
    float4 xv = x4[t], hv = h4[t];
    const float4* wi0 = (const float4*)(W_ih + (size_t)i * H);
    const float4* wi1 = (const float4*)(W_ih + (size_t)(i + H) * H);
    const float4* wi2 = (const float4*)(W_ih + (size_t)(i + 2*H) * H);
    const float4* wh0 = (const float4*)(W_hh + (size_t)i * H);
    const float4* wh1 = (const float4*)(W_hh + (size_t)(i + H) * H);
    const float4* wh2 = (const float4*)(W_hh + (size_t)(i + 2*H) * H);
    float a0 = dot4(wi0[t], xv);
    float a1 = dot4(wi1[t], xv);
    float a2 = dot4(wi2[t], xv);
    float a3 = dot4(wh0[t], hv);
    float a4 = dot4(wh1[t], hv);
    float a5 = dot4(wh2[t], hv);
    a0 = warp_sum(a0); a1 = warp_sum(a1); a2 = warp_sum(a2);
    a3 = warp_sum(a3); a4 = warp_sum(a4); a5 = warp_sum(a5);
    __shared__ float sm[6][8];
    if ((t & 31) == 0) {
        int w = t >> 5;
        sm[0][w] = a0; sm[1][w] = a1; sm[2][w] = a2;
        sm[3][w] = a3; sm[4][w] = a4; sm[5][w] = a5;
    }
    __syncthreads();
    if (t == 0) {
        float s0=0,s1=0,s2=0,s3=0,s4=0,s5=0;
        #pragma unroll
        for (int w = 0; w < 8; ++w) {
            s0 += sm[0][w]; s1 += sm[1][w]; s2 += sm[2][w];
            s3 += sm[3][w]; s4 += sm[4][w]; s5 += sm[5][w];
        }
        float gi_r = s0 + b_ih[i];
        float gi_z = s1 + b_ih[i + H];
        float gi_n = s2 + b_ih[i + 2*H];
        float gh_r = s3 + b_hh[i];
        float gh_z = s4 + b_hh[i + H];
        float gh_n = s5 + b_hh[i + 2*H];
        float r = 1.f / (1.f + expf(-(gi_r + gh_r)));
        float z = 1.f / (1.f + expf(-(gi_z + gh_z)));
        float n = tanhf(gi_n + r * gh_n);
        float hn = (1.f - z) * n + z * h[i];
        g_hnew[i] = hn;
        d_out[V + i] = hn;
    }
}

// ---- k6: logits[v] = out_W[v,:] . h_new + out_b[v]  (the 206 MB GEMV) ----
__global__ void k_logits(const float* __restrict__ out_W,
                         const float* __restrict__ out_b) {
    int v = blockIdx.x;                 // 0..V-1
    int t = threadIdx.x;                // 128 threads
    const float4* w4 = (const float4*)(out_W + (size_t)v * H);
    const float4* h4 = (const float4*)g_hnew;
    float acc = dot4(w4[t], h4[t]) + dot4(w4[t + 128], h4[t + 128]);
    acc = warp_sum(acc);
    __shared__ float sm[4];
    if ((t & 31) == 0) sm[t >> 5] = acc;
    __syncthreads();
    if (t == 0)
        g_logits[v] = sm[0] + sm[1] + sm[2] + sm[3] + out_b[v];
}

// ---- k7: max + log-sum-exp over V (single block, deterministic) ----
__global__ void k_lse() {
    int t = threadIdx.x;                // 1024 threads
    __shared__ float sm[1024];
    float m = -INFINITY;
    for (int v = t; v < V; v += 1024) m = fmaxf(m, g_logits[v]);
    sm[t] = m; __syncthreads();
    #pragma unroll
    for (int o = 512; o > 0; o >>= 1) {
        if (t < o) sm[t] = fmaxf(sm[t], sm[t + o]);
        __syncthreads();
    }
    m = sm[0];
    __syncthreads();
    float s = 0.f;
    for (int v = t; v < V; v += 1024) s += expf(g_logits[v] - m);
    sm[t] = s; __syncthreads();
    #pragma unroll
    for (int o = 512; o > 0; o >>= 1) {
        if (t < o) sm[t] += sm[t + o];
        __syncthreads();
    }
    if (t == 0) { g_red[0] = m; g_red[1] = logf(sm[0]); }
}

// ---- k8: out[v] = logits[v] - m - lse ----
__global__ void k_norm(float* __restrict__ d_out) {
    int v = blockIdx.x * 256 + threadIdx.x;
    if (v < V) d_out[v] = g_logits[v] - g_red[0] - g_red[1];
}

extern "C" void kernel_launch(void* const* d_in, const int* in_sizes, int n_in,
                              void* d_out, int out_size) {
    const int*   idx    = (const int*)  d_in[0];
    const float* hidden = (const float*)d_in[1];
    const float* enc    = (const float*)d_in[2];
    const float* emb    = (const float*)d_in[3];
    const float* attn_W = (const float*)d_in[4];
    const float* attn_b = (const float*)d_in[5];
    const float* comb_W = (const float*)d_in[6];
    const float* comb_b = (const float*)d_in[7];
    const float* W_ih   = (const float*)d_in[8];
    const float* W_hh   = (const float*)d_in[9];
    const float* b_ih   = (const float*)d_in[10];
    const float* b_hh   = (const float*)d_in[11];
    const float* out_W  = (const float*)d_in[12];
    const float* out_b  = (const float*)d_in[13];
    float* out = (float*)d_out;

    k_scores <<<L, 256>>>(idx, emb, hidden, attn_W, attn_b);
    k_softmax<<<1, 512>>>(out);
    k_ctx    <<<4, 256>>>(enc);
    k_combine<<<H, 256>>>(idx, emb, comb_W, comb_b);
    k_gru    <<<H, 256>>>(hidden, W_ih, W_hh, b_ih, b_hh, out);
    k_logits <<<V, 128>>>(out_W, out_b);
    k_lse    <<<1, 1024>>>();
    k_norm   <<<(V + 255) / 256, 256>>>(out);
}

// round 4
// speedup vs baseline: 1.3508x; 1.3508x over previous
#include <cuda_runtime.h>
#include <math.h>

#define H 1024
#define V 50257
#define L 512
#define NB ((V + 7) / 8)   // 6283 logits blocks, 8 rows each

// ---------------- scratch (no allocations allowed) ----------------
__device__ float g_scores[L];        // attn scores, then attn weights
__device__ float g_ctxp[8 * H];      // 8 partial context vectors
__device__ float g_x[H];             // GRU input
__device__ float g_hnew[H];          // new hidden
__device__ float g_logits[V];
__device__ float g_pmax[NB];         // per-block max of logits
__device__ float g_psum[NB];         // per-block sum exp(logit - pmax)
__device__ float g_red[2];           // global max, log(sumexp)

__device__ __forceinline__ float warp_sum(float v) {
    #pragma unroll
    for (int o = 16; o > 0; o >>= 1) v += __shfl_down_sync(0xffffffffu, v, o);
    return v;
}
__device__ __forceinline__ float dot4(float4 a, float4 b) {
    return a.x*b.x + a.y*b.y + a.z*b.z + a.w*b.w;
}

// ---- k1: attn scores. 8 warps/block, warp-per-row. grid = L/8 = 64 ----
__global__ void __launch_bounds__(256)
k_scores(const int* __restrict__ idx,
         const float* __restrict__ emb,
         const float* __restrict__ h,
         const float* __restrict__ attn_W,
         const float* __restrict__ attn_b) {
    __shared__ float cat_sh[2 * H];
    int t = threadIdx.x;                       // 256
    const float4* e4 = (const float4*)(emb + (size_t)idx[0] * H);
    const float4* h4 = (const float4*)h;
    ((float4*)cat_sh)[t]       = e4[t];
    ((float4*)cat_sh)[t + 256] = h4[t];
    __syncthreads();
    int warp = t >> 5, lane = t & 31;
    int l = blockIdx.x * 8 + warp;
    const float4* w4 = (const float4*)(attn_W + (size_t)l * (2 * H));
    const float4* c4 = (const float4*)cat_sh;
    float acc = 0.f;
    #pragma unroll
    for (int k = 0; k < 16; ++k) {
        int j = lane + 32 * k;
        acc += dot4(w4[j], c4[j]);
    }
    acc = warp_sum(acc);
    if (lane == 0) g_scores[l] = acc + attn_b[l];
}

// ---- k2: softmax over L=512 ----
__global__ void __launch_bounds__(512)
k_softmax(float* __restrict__ d_out) {
    int t = threadIdx.x;                       // 512
    __shared__ float sm[512];
    float s = g_scores[t];
    sm[t] = s; __syncthreads();
    #pragma unroll
    for (int o = 256; o > 0; o >>= 1) {
        if (t < o) sm[t] = fmaxf(sm[t], sm[t + o]);
        __syncthreads();
    }
    float m = sm[0];
    __syncthreads();
    float e = expf(s - m);
    sm[t] = e; __syncthreads();
    #pragma unroll
    for (int o = 256; o > 0; o >>= 1) {
        if (t < o) sm[t] += sm[t + o];
        __syncthreads();
    }
    float w = e / sm[0];
    g_scores[t] = w;
    d_out[V + H + t] = w;
}

// ---- k3: partial ctx. grid (8 colblocks, 8 L-chunks), 128 threads ----
__global__ void __launch_bounds__(128)
k_ctx(const float* __restrict__ enc) {
    __shared__ float wsh[64];
    int t = threadIdx.x;
    int cb = blockIdx.x, lc = blockIdx.y;
    if (t < 64) wsh[t] = g_scores[lc * 64 + t];
    __syncthreads();
    int col = cb * 128 + t;
    const float* e = enc + (size_t)(lc * 64) * H + col;
    float acc = 0.f;
    #pragma unroll 8
    for (int j = 0; j < 64; ++j)
        acc += wsh[j] * e[(size_t)j * H];
    g_ctxp[lc * H + col] = acc;
}

// ---- k4: combine + relu. warp-per-row, grid = H/8 = 128 ----
__global__ void __launch_bounds__(256)
k_combine(const int* __restrict__ idx,
          const float* __restrict__ emb,
          const float* __restrict__ comb_W,
          const float* __restrict__ comb_b) {
    __shared__ float cat_sh[2 * H];
    int t = threadIdx.x;                       // 256
    const float4* e4 = (const float4*)(emb + (size_t)idx[0] * H);
    ((float4*)cat_sh)[t] = e4[t];
    float4 c = make_float4(0.f, 0.f, 0.f, 0.f);
    #pragma unroll
    for (int p = 0; p < 8; ++p) {
        float4 v = ((const float4*)(g_ctxp + p * H))[t];
        c.x += v.x; c.y += v.y; c.z += v.z; c.w += v.w;
    }
    ((float4*)cat_sh)[t + 256] = c;
    __syncthreads();
    int warp = t >> 5, lane = t & 31;
    int i = blockIdx.x * 8 + warp;
    const float4* w4 = (const float4*)(comb_W + (size_t)i * (2 * H));
    const float4* c4 = (const float4*)cat_sh;
    float acc = 0.f;
    #pragma unroll
    for (int k = 0; k < 16; ++k) {
        int j = lane + 32 * k;
        acc += dot4(w4[j], c4[j]);
    }
    acc = warp_sum(acc);
    if (lane == 0) g_x[i] = fmaxf(acc + comb_b[i], 0.f);
}

// ---- k5: GRU. warp-per-output, grid = H/8 = 128 ----
__global__ void __launch_bounds__(256)
k_gru(const float* __restrict__ h,
      const float* __restrict__ W_ih,
      const float* __restrict__ W_hh,
      const float* __restrict__ b_ih,
      const float* __restrict__ b_hh,
      float* __restrict__ d_out) {
    __shared__ float x_sh[H], h_sh[H];
    int t = threadIdx.x;                       // 256
    ((float4*)x_sh)[t] = ((const float4*)g_x)[t];
    ((float4*)h_sh)[t] = ((const float4*)h)[t];
    __syncthreads();
    int warp = t >> 5, lane = t & 31;
    int i = blockIdx.x * 8 + warp;
    const float4* x4 = (const float4*)x_sh;
    const float4* h4 = (const float4*)h_sh;
    const float4* wi0 = (const float4*)(W_ih + (size_t)i * H);
    const float4* wi1 = (const float4*)(W_ih + (size_t)(i + H) * H);
    const float4* wi2 = (const float4*)(W_ih + (size_t)(i + 2 * H) * H);
    const float4* wh0 = (const float4*)(W_hh + (size_t)i * H);
    const float4* wh1 = (const float4*)(W_hh + (size_t)(i + H) * H);
    const float4* wh2 = (const float4*)(W_hh + (size_t)(i + 2 * H) * H);
    float a0 = 0.f, a1 = 0.f, a2 = 0.f, a3 = 0.f, a4 = 0.f, a5 = 0.f;
    #pragma unroll
    for (int k = 0; k < 8; ++k) {
        int j = lane + 32 * k;
        float4 xv = x4[j], hv = h4[j];
        a0 += dot4(wi0[j], xv);
        a1 += dot4(wi1[j], xv);
        a2 += dot4(wi2[j], xv);
        a3 += dot4(wh0[j], hv);
        a4 += dot4(wh1[j], hv);
        a5 += dot4(wh2[j], hv);
    }
    a0 = warp_sum(a0); a1 = warp_sum(a1); a2 = warp_sum(a2);
    a3 = warp_sum(a3); a4 = warp_sum(a4); a5 = warp_sum(a5);
    if (lane == 0) {
        float gi_r = a0 + b_ih[i];
        float gi_z = a1 + b_ih[i + H];
        float gi_n = a2 + b_ih[i + 2 * H];
        float gh_r = a3 + b_hh[i];
        float gh_z = a4 + b_hh[i + H];
        float gh_n = a5 + b_hh[i + 2 * H];
        float r = 1.f / (1.f + expf(-(gi_r + gh_r)));
        float z = 1.f / (1.f + expf(-(gi_z + gh_z)));
        float n = tanhf(gi_n + r * gh_n);
        float hn = (1.f - z) * n + z * h[i];
        g_hnew[i] = hn;
        d_out[V + i] = hn;
    }
}

// ---- k6: logits GEMV + per-block partial (max, sumexp). warp-per-row ----
__global__ void __launch_bounds__(256)
k_logits(const float* __restrict__ out_W,
         const float* __restrict__ out_b) {
    __shared__ float h_sh[H];
    __shared__ float wval[8];
    int t = threadIdx.x;                       // 256
    ((float4*)h_sh)[t] = ((const float4*)g_hnew)[t];
    __syncthreads();
    int warp = t >> 5, lane = t & 31;
    int r = blockIdx.x * 8 + warp;
    if (r < V) {
        const float4* w4 = (const float4*)(out_W + (size_t)r * H);
        const float4* h4 = (const float4*)h_sh;
        float acc = 0.f;
        #pragma unroll
        for (int k = 0; k < 8; ++k) {
            int j = lane + 32 * k;
            acc += dot4(w4[j], h4[j]);
        }
        acc = warp_sum(acc);
        if (lane == 0) {
            acc += out_b[r];
            g_logits[r] = acc;
            wval[warp] = acc;
        }
    }
    __syncthreads();
    // warp 0 reduces the (up to) 8 row values to a (max, sumexp) partial
    if (warp == 0) {
        int nv = V - blockIdx.x * 8;
        if (nv > 8) nv = 8;
        float v = (lane < nv) ? wval[lane] : -INFINITY;
        float m = v;
        #pragma unroll
        for (int o = 4; o > 0; o >>= 1)
            m = fmaxf(m, __shfl_down_sync(0xffffffffu, m, o));
        m = __shfl_sync(0xffffffffu, m, 0);
        float e = (lane < nv) ? expf(v - m) : 0.f;
        #pragma unroll
        for (int o = 4; o > 0; o >>= 1)
            e += __shfl_down_sync(0xffffffffu, e, o);
        if (lane == 0) {
            g_pmax[blockIdx.x] = m;
            g_psum[blockIdx.x] = e;
        }
    }
}

// ---- k7: combine 6283 partials -> global max + log(sumexp) ----
__global__ void __launch_bounds__(1024)
k_lse() {
    int t = threadIdx.x;                       // 1024
    __shared__ float sm[1024];
    float m = -INFINITY;
    for (int i = t; i < NB; i += 1024) m = fmaxf(m, g_pmax[i]);
    sm[t] = m; __syncthreads();
    #pragma unroll
    for (int o = 512; o > 0; o >>= 1) {
        if (t < o) sm[t] = fmaxf(sm[t], sm[t + o]);
        __syncthreads();
    }
    m = sm[0];
    __syncthreads();
    float s = 0.f;
    for (int i = t; i < NB; i += 1024) s += g_psum[i] * expf(g_pmax[i] - m);
    sm[t] = s; __syncthreads();
    #pragma unroll
    for (int o = 512; o > 0; o >>= 1) {
        if (t < o) sm[t] += sm[t + o];
        __syncthreads();
    }
    if (t == 0) { g_red[0] = m; g_red[1] = logf(sm[0]); }
}

// ---- k8: out[v] = logits[v] - m - lse ----
__global__ void __launch_bounds__(256)
k_norm(float* __restrict__ d_out) {
    int v = blockIdx.x * 256 + threadIdx.x;
    if (v < V) d_out[v] = g_logits[v] - g_red[0] - g_red[1];
}

extern "C" void kernel_launch(void* const* d_in, const int* in_sizes, int n_in,
                              void* d_out, int out_size) {
    const int*   idx    = (const int*)  d_in[0];
    const float* hidden = (const float*)d_in[1];
    const float* enc    = (const float*)d_in[2];
    const float* emb    = (const float*)d_in[3];
    const float* attn_W = (const float*)d_in[4];
    const float* attn_b = (const float*)d_in[5];
    const float* comb_W = (const float*)d_in[6];
    const float* comb_b = (const float*)d_in[7];
    const float* W_ih   = (const float*)d_in[8];
    const float* W_hh   = (const float*)d_in[9];
    const float* b_ih   = (const float*)d_in[10];
    const float* b_hh   = (const float*)d_in[11];
    const float* out_W  = (const float*)d_in[12];
    const float* out_b  = (const float*)d_in[13];
    float* out = (float*)d_out;

    k_scores <<<L / 8, 256>>>(idx, emb, hidden, attn_W, attn_b);
    k_softmax<<<1, 512>>>(out);
    k_ctx    <<<dim3(8, 8), 128>>>(enc);
    k_combine<<<H / 8, 256>>>(idx, emb, comb_W, comb_b);
    k_gru    <<<H / 8, 256>>>(hidden, W_ih, W_hh, b_ih, b_hh, out);
    k_logits <<<NB, 256>>>(out_W, out_b);
    k_lse    <<<1, 1024>>>();
    k_norm   <<<(V + 255) / 256, 256>>>(out);
}